// round 11
// baseline (speedup 1.0000x reference)
#include <cuda_runtime.h>
#include <cuda_bf16.h>
#include <cstdint>

// Problem constants (fixed by the reference)
constexpr int NNODES = 100000;
constexpr int NEDGES = 600000;
constexpr int F_IN  = 128;
constexpr int F_L1  = 96;
constexpr int F_L2  = 64;
constexpr int F_OUT = 32;

// ---------------- scratch (device globals; no allocations allowed) ----------
__device__ float g_y [(size_t)NNODES * F_L1];   // neighbor-branch GEMM out (96 then 64)
__device__ float g_r [(size_t)NNODES * F_L1];   // root-branch GEMM out
__device__ float g_h1[(size_t)NNODES * F_L1];   // layer-1 activations
__device__ float g_h2[(size_t)NNODES * F_L2];   // layer-2 activations
__device__ float g_m [(size_t)NNODES * F_OUT];  // mu head pre-aggregation (dis-prescaled)
__device__ float g_l [(size_t)NNODES * F_OUT];  // logstd head pre-aggregation

__device__ float g_dinv[NNODES];
__device__ float g_dis [NNODES];
__device__ int   g_degcnt[NNODES];
__device__ int   g_rowstart[NNODES + 1];
__device__ int   g_pos[NNODES];
__device__ int   g_csr[NEDGES];

// ---------------- CSR build ----------------
__global__ void init_deg_kernel() {
    int i = blockIdx.x * blockDim.x + threadIdx.x;
    if (i < NNODES) g_degcnt[i] = 0;
}

__global__ void count_deg_kernel(const int* __restrict__ dst) {
    int e = blockIdx.x * blockDim.x + threadIdx.x;
    if (e < NEDGES) atomicAdd(&g_degcnt[dst[e]], 1);
}

// Single-block exclusive scan over degcnt (100k elems; 1024 threads x ~98 each).
__global__ void scan_kernel() {
    __shared__ int sh[1024];
    const int t = threadIdx.x;
    const int CH = (NNODES + 1023) / 1024;   // 98
    const int begin = t * CH;
    const int end = min(begin + CH, NNODES);

    int s = 0;
    for (int i = begin; i < end; i++) s += g_degcnt[i];
    sh[t] = s;
    __syncthreads();

    for (int off = 1; off < 1024; off <<= 1) {
        int add = (t >= off) ? sh[t - off] : 0;
        __syncthreads();
        sh[t] += add;
        __syncthreads();
    }

    int run = (t > 0) ? sh[t - 1] : 0;   // exclusive base
    for (int i = begin; i < end; i++) {
        g_rowstart[i] = run;
        g_pos[i] = run;
        run += g_degcnt[i];
        float deg = (float)(g_degcnt[i] + 1);  // + self loop
        g_dinv[i] = 1.0f / deg;
        g_dis[i]  = rsqrtf(deg);
    }
    if (t == 1023) g_rowstart[NNODES] = run;   // == NEDGES
}

__global__ void fill_csr_kernel(const int* __restrict__ src, const int* __restrict__ dst) {
    int e = blockIdx.x * blockDim.x + threadIdx.x;
    if (e < NEDGES) {
        int d = dst[e];
        int idx = atomicAdd(&g_pos[d], 1);
        g_csr[idx] = src[e];
    }
}

// ---------------- tensor-core GEMM (bf16 hi/lo 3-MMA split) -----------------
// C[N rows, Nw cols] = A[rows, K] @ [B0 | B1]   (B0,B1 each [K, Nw/2] row-major)
// Columns [0, Nw/2) -> Cy, columns [Nw/2, Nw) -> Cr. Optional per-row scale.
// Block: 256 threads = 8 warps (4 m-groups x 2 n-groups), BM=128, full K resident.

__device__ __forceinline__ void mma_bf16(float* c, uint32_t a0, uint32_t a1,
                                         uint32_t a2, uint32_t a3,
                                         uint32_t b0, uint32_t b1) {
    asm volatile(
        "mma.sync.aligned.m16n8k16.row.col.f32.bf16.bf16.f32 "
        "{%0,%1,%2,%3}, {%4,%5,%6,%7}, {%8,%9}, {%0,%1,%2,%3};\n"
        : "+f"(c[0]), "+f"(c[1]), "+f"(c[2]), "+f"(c[3])
        : "r"(a0), "r"(a1), "r"(a2), "r"(a3), "r"(b0), "r"(b1));
}

template <int K, int NW, bool ROWSCALE>
__global__ __launch_bounds__(256, 1)
void mma_gemm_kernel(const float* __restrict__ A,
                     const float* __restrict__ B0, const float* __restrict__ B1,
                     const float* __restrict__ rowscale,
                     float* __restrict__ Cy, float* __restrict__ Cr) {
    constexpr int KP = K + 8;          // pad: word-stride/row = (K+8)/2 ≡ 4 (mod 32)
    constexpr int HN = NW / 2;
    constexpr int NT = HN / 8;         // n8 tiles per warp
    static_assert(K % 16 == 0 && HN % 8 == 0, "");

    extern __shared__ __nv_bfloat16 sm[];
    __nv_bfloat16* Ah = sm;
    __nv_bfloat16* Al = Ah + 128 * KP;
    __nv_bfloat16* Bh = Al + 128 * KP;   // B stored transposed: [n][k]
    __nv_bfloat16* Bl = Bh + NW * KP;

    const int tid  = threadIdx.x;
    const int row0 = blockIdx.x * 128;

    // ---- load A tile (128 x K), split into hi/lo bf16 ----
    for (int idx = tid; idx < 128 * (K / 4); idx += 256) {
        int row = idx / (K / 4);
        int kq  = (idx % (K / 4)) * 4;
        float4 v = make_float4(0.f, 0.f, 0.f, 0.f);
        if (row0 + row < NNODES)
            v = *reinterpret_cast<const float4*>(A + (size_t)(row0 + row) * K + kq);
        float f[4] = {v.x, v.y, v.z, v.w};
        __nv_bfloat16 h[4], l[4];
#pragma unroll
        for (int q = 0; q < 4; q++) {
            h[q] = __float2bfloat16(f[q]);
            l[q] = __float2bfloat16(f[q] - __bfloat162float(h[q]));
        }
        *reinterpret_cast<uint2*>(&Ah[row * KP + kq]) = *reinterpret_cast<uint2*>(h);
        *reinterpret_cast<uint2*>(&Al[row * KP + kq]) = *reinterpret_cast<uint2*>(l);
    }

    // ---- load [B0|B1] transposed (NW x K), hi/lo, u32-vectorized stores ----
    for (int idx = tid; idx < NW * (K / 2); idx += 256) {
        int kk = idx / NW;           // k pair index
        int n  = idx % NW;           // coalesced over lanes
        int k  = kk * 2;
        float w0, w1;
        if (n < HN) { w0 = B0[(size_t)k * HN + n];        w1 = B0[(size_t)(k + 1) * HN + n]; }
        else        { w0 = B1[(size_t)k * HN + (n - HN)]; w1 = B1[(size_t)(k + 1) * HN + (n - HN)]; }
        __nv_bfloat16 h[2], l[2];
        h[0] = __float2bfloat16(w0); l[0] = __float2bfloat16(w0 - __bfloat162float(h[0]));
        h[1] = __float2bfloat16(w1); l[1] = __float2bfloat16(w1 - __bfloat162float(h[1]));
        *reinterpret_cast<uint32_t*>(&Bh[n * KP + k]) = *reinterpret_cast<uint32_t*>(h);
        *reinterpret_cast<uint32_t*>(&Bl[n * KP + k]) = *reinterpret_cast<uint32_t*>(l);
    }
    __syncthreads();

    // ---- warp tiling ----
    const int w    = tid >> 5;
    const int lane = tid & 31;
    const int wm   = w & 3;          // 4 row groups of 32
    const int wn   = w >> 2;         // 2 col groups of HN
    const int g    = lane >> 2;      // 0..7
    const int t    = lane & 3;       // 0..3

    float acc[2][NT][4];
#pragma unroll
    for (int mt = 0; mt < 2; mt++)
#pragma unroll
        for (int nt = 0; nt < NT; nt++)
#pragma unroll
            for (int q = 0; q < 4; q++) acc[mt][nt][q] = 0.f;

    for (int k0 = 0; k0 < K; k0 += 16) {
        uint32_t ah[2][4], al[2][4];
#pragma unroll
        for (int mt = 0; mt < 2; mt++) {
            int r = wm * 32 + mt * 16 + g;
            const __nv_bfloat16* ph = Ah + r * KP + k0;
            const __nv_bfloat16* pl = Al + r * KP + k0;
            ah[mt][0] = *reinterpret_cast<const uint32_t*>(ph + 2 * t);
            ah[mt][1] = *reinterpret_cast<const uint32_t*>(ph + 8 * KP + 2 * t);
            ah[mt][2] = *reinterpret_cast<const uint32_t*>(ph + 2 * t + 8);
            ah[mt][3] = *reinterpret_cast<const uint32_t*>(ph + 8 * KP + 2 * t + 8);
            al[mt][0] = *reinterpret_cast<const uint32_t*>(pl + 2 * t);
            al[mt][1] = *reinterpret_cast<const uint32_t*>(pl + 8 * KP + 2 * t);
            al[mt][2] = *reinterpret_cast<const uint32_t*>(pl + 2 * t + 8);
            al[mt][3] = *reinterpret_cast<const uint32_t*>(pl + 8 * KP + 2 * t + 8);
        }
#pragma unroll
        for (int nt = 0; nt < NT; nt++) {
            int n = wn * HN + nt * 8 + g;
            const __nv_bfloat16* qh = Bh + n * KP + k0;
            const __nv_bfloat16* ql = Bl + n * KP + k0;
            uint32_t bh0 = *reinterpret_cast<const uint32_t*>(qh + 2 * t);
            uint32_t bh1 = *reinterpret_cast<const uint32_t*>(qh + 2 * t + 8);
            uint32_t bl0 = *reinterpret_cast<const uint32_t*>(ql + 2 * t);
            uint32_t bl1 = *reinterpret_cast<const uint32_t*>(ql + 2 * t + 8);
#pragma unroll
            for (int mt = 0; mt < 2; mt++) {
                mma_bf16(acc[mt][nt], ah[mt][0], ah[mt][1], ah[mt][2], ah[mt][3], bh0, bh1);
                mma_bf16(acc[mt][nt], ah[mt][0], ah[mt][1], ah[mt][2], ah[mt][3], bl0, bl1);
                mma_bf16(acc[mt][nt], al[mt][0], al[mt][1], al[mt][2], al[mt][3], bh0, bh1);
            }
        }
    }

    // ---- epilogue ----
    float* Cout = wn ? Cr : Cy;
#pragma unroll
    for (int mt = 0; mt < 2; mt++) {
        int r0 = row0 + wm * 32 + mt * 16 + g;
        int r1 = r0 + 8;
        float s0 = 1.f, s1 = 1.f;
        if (ROWSCALE) {
            if (r0 < NNODES) s0 = rowscale[r0];
            if (r1 < NNODES) s1 = rowscale[r1];
        }
#pragma unroll
        for (int nt = 0; nt < NT; nt++) {
            int c = nt * 8 + 2 * t;
            if (r0 < NNODES) {
                float2 v = make_float2(acc[mt][nt][0] * s0, acc[mt][nt][1] * s0);
                *reinterpret_cast<float2*>(&Cout[(size_t)r0 * HN + c]) = v;
            }
            if (r1 < NNODES) {
                float2 v = make_float2(acc[mt][nt][2] * s1, acc[mt][nt][3] * s1);
                *reinterpret_cast<float2*>(&Cout[(size_t)r1 * HN + c]) = v;
            }
        }
    }
}

// ---------------- aggregation (gather, atomic-free) ----------------
// ClusterGCN layer: out = relu( dinv[i]*(y[i] + sum_{j->i} y[j]) + r[i] + b )
template <int F>
__launch_bounds__(256)
__global__ void layer_gather_kernel(const float* __restrict__ y, const float* __restrict__ r,
                                    const float* __restrict__ bias, float* __restrict__ out) {
    const int node = (blockIdx.x * blockDim.x + threadIdx.x) >> 5;
    const int lane = threadIdx.x & 31;
    if (node >= NNODES) return;
    constexpr int C = F / 32;

    float acc[C];
    const float* yi = y + (size_t)node * F;
#pragma unroll
    for (int c = 0; c < C; c++) acc[c] = yi[lane + 32 * c];   // self loop

    const int s = g_rowstart[node];
    const int e = g_rowstart[node + 1];
    for (int p = s; p < e; p++) {
        int j = __ldg(&g_csr[p]);
        const float* yj = y + (size_t)j * F;
#pragma unroll
        for (int c = 0; c < C; c++) acc[c] += __ldg(yj + lane + 32 * c);
    }

    const float di = g_dinv[node];
#pragma unroll
    for (int c = 0; c < C; c++) {
        int f = lane + 32 * c;
        float v = fmaf(di, acc[c], r[(size_t)node * F + f] + bias[f]);
        out[(size_t)node * F + f] = fmaxf(v, 0.f);
    }
}

// Both GCN heads fused: hm/hl prescaled by dis[src]; out = dis[i]*(h[i]+sum h[j]) + b
__launch_bounds__(256)
__global__ void head_gather2_kernel(const float* __restrict__ hm, const float* __restrict__ hl,
                                    const float* __restrict__ bmu, const float* __restrict__ bls,
                                    float* __restrict__ out) {
    const int node = (blockIdx.x * blockDim.x + threadIdx.x) >> 5;
    const int lane = threadIdx.x & 31;
    if (node >= NNODES) return;

    float am = hm[(size_t)node * 32 + lane];
    float al = hl[(size_t)node * 32 + lane];

    const int s = g_rowstart[node];
    const int e = g_rowstart[node + 1];
    for (int p = s; p < e; p++) {
        int j = __ldg(&g_csr[p]);
        am += __ldg(hm + (size_t)j * 32 + lane);
        al += __ldg(hl + (size_t)j * 32 + lane);
    }

    const float di = g_dis[node];
    out[(size_t)node * 32 + lane] = fmaf(di, am, bmu[lane]);
    out[(size_t)NNODES * 32 + (size_t)node * 32 + lane] = fmaf(di, al, bls[lane]);
}

// ---------------- launch ----------------
extern "C" void kernel_launch(void* const* d_in, const int* in_sizes, int n_in,
                              void* d_out, int out_size) {
    (void)in_sizes; (void)n_in; (void)out_size;

    const float* x   = (const float*)d_in[0];
    const int*   ei  = (const int*)d_in[1];
    const float* W1  = (const float*)d_in[2];
    const float* b1  = (const float*)d_in[3];
    const float* Wr1 = (const float*)d_in[4];
    const float* W2  = (const float*)d_in[5];
    const float* b2  = (const float*)d_in[6];
    const float* Wr2 = (const float*)d_in[7];
    const float* Wmu = (const float*)d_in[8];
    const float* bmu = (const float*)d_in[9];
    const float* Wls = (const float*)d_in[10];
    const float* bls = (const float*)d_in[11];
    float* out = (float*)d_out;

    const int* src = ei;
    const int* dst = ei + NEDGES;

    // dynamic smem sizes: (2*128 + 2*NW) * (K+8) * sizeof(bf16)
    constexpr int SM1 = (256 + 2 * 192) * (F_IN + 8) * 2;   // 174080
    constexpr int SM2 = (256 + 2 * 128) * (F_L1 + 8) * 2;   // 106496
    constexpr int SM3 = (256 + 2 * 64)  * (F_L2 + 8) * 2;   //  55296

    static float *p_y = nullptr, *p_r = nullptr, *p_h1 = nullptr, *p_h2 = nullptr,
                 *p_m = nullptr, *p_l = nullptr, *p_dis = nullptr;
    if (!p_y) {  // one-time address lookup + smem opt-in (no allocations, no stream ops)
        cudaGetSymbolAddress((void**)&p_y,  g_y);
        cudaGetSymbolAddress((void**)&p_r,  g_r);
        cudaGetSymbolAddress((void**)&p_h1, g_h1);
        cudaGetSymbolAddress((void**)&p_h2, g_h2);
        cudaGetSymbolAddress((void**)&p_m,  g_m);
        cudaGetSymbolAddress((void**)&p_l,  g_l);
        cudaGetSymbolAddress((void**)&p_dis, g_dis);
        cudaFuncSetAttribute(mma_gemm_kernel<F_IN, 192, false>,
                             cudaFuncAttributeMaxDynamicSharedMemorySize, SM1);
        cudaFuncSetAttribute(mma_gemm_kernel<F_L1, 128, false>,
                             cudaFuncAttributeMaxDynamicSharedMemorySize, SM2);
        cudaFuncSetAttribute(mma_gemm_kernel<F_L2, 64, true>,
                             cudaFuncAttributeMaxDynamicSharedMemorySize, SM3);
    }

    constexpr int TB = 256;
    const int gridN  = (NNODES + TB - 1) / TB;
    const int gridE  = (NEDGES + TB - 1) / TB;
    const int gridGM = (NNODES + 127) / 128;                 // GEMM row blocks
    const int gridGA = ((size_t)NNODES * 32 + TB - 1) / TB;  // 1 warp / node

    // 1) CSR + normalization factors
    init_deg_kernel<<<gridN, TB>>>();
    count_deg_kernel<<<gridE, TB>>>(dst);
    scan_kernel<<<1, 1024>>>();
    fill_csr_kernel<<<gridE, TB>>>(src, dst);

    // 2) layer 1: [y|r] = x @ [W1|Wr1], gather+relu
    mma_gemm_kernel<F_IN, 192, false><<<gridGM, TB, SM1>>>(x, W1, Wr1, nullptr, p_y, p_r);
    layer_gather_kernel<F_L1><<<gridGA, TB>>>(p_y, p_r, b1, p_h1);

    // 3) layer 2
    mma_gemm_kernel<F_L1, 128, false><<<gridGM, TB, SM2>>>(p_h1, W2, Wr2, nullptr, p_y, p_r);
    layer_gather_kernel<F_L2><<<gridGA, TB>>>(p_y, p_r, b2, p_h2);

    // 4) GCN heads: one fused GEMM (dis-prescaled rows) + one fused gather
    mma_gemm_kernel<F_L2, 64, true><<<gridGM, TB, SM3>>>(p_h2, Wmu, Wls, p_dis, p_m, p_l);
    head_gather2_kernel<<<gridGA, TB>>>(p_m, p_l, bmu, bls, out);
}

// round 12
// speedup vs baseline: 1.0100x; 1.0100x over previous
#include <cuda_runtime.h>
#include <cuda_bf16.h>
#include <cstdint>

// Problem constants (fixed by the reference)
constexpr int NNODES = 100000;
constexpr int NEDGES = 600000;
constexpr int F_IN  = 128;
constexpr int F_L1  = 96;
constexpr int F_L2  = 64;
constexpr int F_OUT = 32;

// ---------------- scratch (device globals; no allocations allowed) ----------
__device__ float g_y [(size_t)NNODES * F_L1];   // neighbor-branch GEMM out (96 then 64)
__device__ float g_r [(size_t)NNODES * F_L1];   // root-branch GEMM out
__device__ float g_h1[(size_t)NNODES * F_L1];   // layer-1 activations
__device__ float g_h2[(size_t)NNODES * F_L2];   // layer-2 activations
__device__ float g_m [(size_t)NNODES * F_OUT];  // mu head pre-aggregation (dis-prescaled)
__device__ float g_l [(size_t)NNODES * F_OUT];  // logstd head pre-aggregation

__device__ float g_dinv[NNODES];
__device__ float g_dis [NNODES];
__device__ int   g_degcnt[NNODES];
__device__ int   g_rowstart[NNODES + 1];
__device__ int   g_pos[NNODES];
__device__ int   g_csr[NEDGES];

// ---------------- CSR build ----------------
__global__ void init_deg_kernel() {
    int i = blockIdx.x * blockDim.x + threadIdx.x;
    if (i < NNODES) g_degcnt[i] = 0;
}

__global__ void count_deg_kernel(const int* __restrict__ dst) {
    int e = blockIdx.x * blockDim.x + threadIdx.x;
    if (e < NEDGES) atomicAdd(&g_degcnt[dst[e]], 1);
}

// Single-block exclusive scan over degcnt (100k elems; 1024 threads x ~98 each).
__global__ void scan_kernel() {
    __shared__ int sh[1024];
    const int t = threadIdx.x;
    const int CH = (NNODES + 1023) / 1024;   // 98
    const int begin = t * CH;
    const int end = min(begin + CH, NNODES);

    int s = 0;
    for (int i = begin; i < end; i++) s += g_degcnt[i];
    sh[t] = s;
    __syncthreads();

    for (int off = 1; off < 1024; off <<= 1) {
        int add = (t >= off) ? sh[t - off] : 0;
        __syncthreads();
        sh[t] += add;
        __syncthreads();
    }

    int run = (t > 0) ? sh[t - 1] : 0;   // exclusive base
    for (int i = begin; i < end; i++) {
        g_rowstart[i] = run;
        g_pos[i] = run;
        run += g_degcnt[i];
        float deg = (float)(g_degcnt[i] + 1);  // + self loop
        g_dinv[i] = 1.0f / deg;
        g_dis[i]  = rsqrtf(deg);
    }
    if (t == 1023) g_rowstart[NNODES] = run;   // == NEDGES
}

__global__ void fill_csr_kernel(const int* __restrict__ src, const int* __restrict__ dst) {
    int e = blockIdx.x * blockDim.x + threadIdx.x;
    if (e < NEDGES) {
        int d = dst[e];
        int idx = atomicAdd(&g_pos[d], 1);
        g_csr[idx] = src[e];
    }
}

// ---------------- tensor-core GEMM (bf16 hi/lo 3-MMA split) -----------------
// C[N rows, Nw cols] = A[rows, K] @ [B0 | B1]   (B0,B1 each [K, Nw/2] row-major)
// Columns [0, Nw/2) -> Cy, columns [Nw/2, Nw) -> Cr. Optional per-row scale.
// Block: 256 threads = 8 warps (4 m-groups x 2 n-groups), BM=128, full K resident.

__device__ __forceinline__ void mma_bf16(float* c, uint32_t a0, uint32_t a1,
                                         uint32_t a2, uint32_t a3,
                                         uint32_t b0, uint32_t b1) {
    asm volatile(
        "mma.sync.aligned.m16n8k16.row.col.f32.bf16.bf16.f32 "
        "{%0,%1,%2,%3}, {%4,%5,%6,%7}, {%8,%9}, {%0,%1,%2,%3};\n"
        : "+f"(c[0]), "+f"(c[1]), "+f"(c[2]), "+f"(c[3])
        : "r"(a0), "r"(a1), "r"(a2), "r"(a3), "r"(b0), "r"(b1));
}

template <int K, int NW, bool ROWSCALE>
__global__ __launch_bounds__(256, 1)
void mma_gemm_kernel(const float* __restrict__ A,
                     const float* __restrict__ B0, const float* __restrict__ B1,
                     const float* __restrict__ rowscale,
                     float* __restrict__ Cy, float* __restrict__ Cr) {
    constexpr int KP = K + 8;          // pad: word-stride/row = (K+8)/2 ≡ 4 (mod 32)
    constexpr int HN = NW / 2;
    constexpr int NT = HN / 8;         // n8 tiles per warp
    static_assert(K % 16 == 0 && HN % 8 == 0, "");

    extern __shared__ __nv_bfloat16 sm[];
    __nv_bfloat16* Ah = sm;
    __nv_bfloat16* Al = Ah + 128 * KP;
    __nv_bfloat16* Bh = Al + 128 * KP;   // B stored transposed: [n][k]
    __nv_bfloat16* Bl = Bh + NW * KP;

    const int tid  = threadIdx.x;
    const int row0 = blockIdx.x * 128;

    // ---- load A tile (128 x K), split into hi/lo bf16 ----
    for (int idx = tid; idx < 128 * (K / 4); idx += 256) {
        int row = idx / (K / 4);
        int kq  = (idx % (K / 4)) * 4;
        float4 v = make_float4(0.f, 0.f, 0.f, 0.f);
        if (row0 + row < NNODES)
            v = *reinterpret_cast<const float4*>(A + (size_t)(row0 + row) * K + kq);
        float f[4] = {v.x, v.y, v.z, v.w};
        __nv_bfloat16 h[4], l[4];
#pragma unroll
        for (int q = 0; q < 4; q++) {
            h[q] = __float2bfloat16(f[q]);
            l[q] = __float2bfloat16(f[q] - __bfloat162float(h[q]));
        }
        *reinterpret_cast<uint2*>(&Ah[row * KP + kq]) = *reinterpret_cast<uint2*>(h);
        *reinterpret_cast<uint2*>(&Al[row * KP + kq]) = *reinterpret_cast<uint2*>(l);
    }

    // ---- load [B0|B1] transposed (NW x K), hi/lo, u32-vectorized stores ----
    for (int idx = tid; idx < NW * (K / 2); idx += 256) {
        int kk = idx / NW;           // k pair index
        int n  = idx % NW;           // coalesced over lanes
        int k  = kk * 2;
        float w0, w1;
        if (n < HN) { w0 = B0[(size_t)k * HN + n];        w1 = B0[(size_t)(k + 1) * HN + n]; }
        else        { w0 = B1[(size_t)k * HN + (n - HN)]; w1 = B1[(size_t)(k + 1) * HN + (n - HN)]; }
        __nv_bfloat16 h[2], l[2];
        h[0] = __float2bfloat16(w0); l[0] = __float2bfloat16(w0 - __bfloat162float(h[0]));
        h[1] = __float2bfloat16(w1); l[1] = __float2bfloat16(w1 - __bfloat162float(h[1]));
        *reinterpret_cast<uint32_t*>(&Bh[n * KP + k]) = *reinterpret_cast<uint32_t*>(h);
        *reinterpret_cast<uint32_t*>(&Bl[n * KP + k]) = *reinterpret_cast<uint32_t*>(l);
    }
    __syncthreads();

    // ---- warp tiling ----
    const int w    = tid >> 5;
    const int lane = tid & 31;
    const int wm   = w & 3;          // 4 row groups of 32
    const int wn   = w >> 2;         // 2 col groups of HN
    const int g    = lane >> 2;      // 0..7
    const int t    = lane & 3;       // 0..3

    float acc[2][NT][4];
#pragma unroll
    for (int mt = 0; mt < 2; mt++)
#pragma unroll
        for (int nt = 0; nt < NT; nt++)
#pragma unroll
            for (int q = 0; q < 4; q++) acc[mt][nt][q] = 0.f;

    for (int k0 = 0; k0 < K; k0 += 16) {
        uint32_t ah[2][4], al[2][4];
#pragma unroll
        for (int mt = 0; mt < 2; mt++) {
            int r = wm * 32 + mt * 16 + g;
            const __nv_bfloat16* ph = Ah + r * KP + k0;
            const __nv_bfloat16* pl = Al + r * KP + k0;
            ah[mt][0] = *reinterpret_cast<const uint32_t*>(ph + 2 * t);
            ah[mt][1] = *reinterpret_cast<const uint32_t*>(ph + 8 * KP + 2 * t);
            ah[mt][2] = *reinterpret_cast<const uint32_t*>(ph + 2 * t + 8);
            ah[mt][3] = *reinterpret_cast<const uint32_t*>(ph + 8 * KP + 2 * t + 8);
            al[mt][0] = *reinterpret_cast<const uint32_t*>(pl + 2 * t);
            al[mt][1] = *reinterpret_cast<const uint32_t*>(pl + 8 * KP + 2 * t);
            al[mt][2] = *reinterpret_cast<const uint32_t*>(pl + 2 * t + 8);
            al[mt][3] = *reinterpret_cast<const uint32_t*>(pl + 8 * KP + 2 * t + 8);
        }
#pragma unroll
        for (int nt = 0; nt < NT; nt++) {
            int n = wn * HN + nt * 8 + g;
            const __nv_bfloat16* qh = Bh + n * KP + k0;
            const __nv_bfloat16* ql = Bl + n * KP + k0;
            uint32_t bh0 = *reinterpret_cast<const uint32_t*>(qh + 2 * t);
            uint32_t bh1 = *reinterpret_cast<const uint32_t*>(qh + 2 * t + 8);
            uint32_t bl0 = *reinterpret_cast<const uint32_t*>(ql + 2 * t);
            uint32_t bl1 = *reinterpret_cast<const uint32_t*>(ql + 2 * t + 8);
#pragma unroll
            for (int mt = 0; mt < 2; mt++) {
                mma_bf16(acc[mt][nt], ah[mt][0], ah[mt][1], ah[mt][2], ah[mt][3], bh0, bh1);
                mma_bf16(acc[mt][nt], ah[mt][0], ah[mt][1], ah[mt][2], ah[mt][3], bl0, bl1);
                mma_bf16(acc[mt][nt], al[mt][0], al[mt][1], al[mt][2], al[mt][3], bh0, bh1);
            }
        }
    }

    // ---- epilogue ----
    float* Cout = wn ? Cr : Cy;
#pragma unroll
    for (int mt = 0; mt < 2; mt++) {
        int r0 = row0 + wm * 32 + mt * 16 + g;
        int r1 = r0 + 8;
        float s0 = 1.f, s1 = 1.f;
        if (ROWSCALE) {
            if (r0 < NNODES) s0 = rowscale[r0];
            if (r1 < NNODES) s1 = rowscale[r1];
        }
#pragma unroll
        for (int nt = 0; nt < NT; nt++) {
            int c = nt * 8 + 2 * t;
            if (r0 < NNODES) {
                float2 v = make_float2(acc[mt][nt][0] * s0, acc[mt][nt][1] * s0);
                *reinterpret_cast<float2*>(&Cout[(size_t)r0 * HN + c]) = v;
            }
            if (r1 < NNODES) {
                float2 v = make_float2(acc[mt][nt][2] * s1, acc[mt][nt][3] * s1);
                *reinterpret_cast<float2*>(&Cout[(size_t)r1 * HN + c]) = v;
            }
        }
    }
}

// ---------------- aggregation (gather, atomic-free) ----------------
// ClusterGCN layer: out = relu( dinv[i]*(y[i] + sum_{j->i} y[j]) + r[i] + b )
template <int F>
__launch_bounds__(256)
__global__ void layer_gather_kernel(const float* __restrict__ y, const float* __restrict__ r,
                                    const float* __restrict__ bias, float* __restrict__ out) {
    const int node = (blockIdx.x * blockDim.x + threadIdx.x) >> 5;
    const int lane = threadIdx.x & 31;
    if (node >= NNODES) return;
    constexpr int C = F / 32;

    float acc[C];
    const float* yi = y + (size_t)node * F;
#pragma unroll
    for (int c = 0; c < C; c++) acc[c] = yi[lane + 32 * c];   // self loop

    const int s = g_rowstart[node];
    const int e = g_rowstart[node + 1];
    for (int p = s; p < e; p++) {
        int j = __ldg(&g_csr[p]);
        const float* yj = y + (size_t)j * F;
#pragma unroll
        for (int c = 0; c < C; c++) acc[c] += __ldg(yj + lane + 32 * c);
    }

    const float di = g_dinv[node];
#pragma unroll
    for (int c = 0; c < C; c++) {
        int f = lane + 32 * c;
        float v = fmaf(di, acc[c], r[(size_t)node * F + f] + bias[f]);
        out[(size_t)node * F + f] = fmaxf(v, 0.f);
    }
}

// Both GCN heads fused: hm/hl prescaled by dis[src]; out = dis[i]*(h[i]+sum h[j]) + b
__launch_bounds__(256)
__global__ void head_gather2_kernel(const float* __restrict__ hm, const float* __restrict__ hl,
                                    const float* __restrict__ bmu, const float* __restrict__ bls,
                                    float* __restrict__ out) {
    const int node = (blockIdx.x * blockDim.x + threadIdx.x) >> 5;
    const int lane = threadIdx.x & 31;
    if (node >= NNODES) return;

    float am = hm[(size_t)node * 32 + lane];
    float al = hl[(size_t)node * 32 + lane];

    const int s = g_rowstart[node];
    const int e = g_rowstart[node + 1];
    for (int p = s; p < e; p++) {
        int j = __ldg(&g_csr[p]);
        am += __ldg(hm + (size_t)j * 32 + lane);
        al += __ldg(hl + (size_t)j * 32 + lane);
    }

    const float di = g_dis[node];
    out[(size_t)node * 32 + lane] = fmaf(di, am, bmu[lane]);
    out[(size_t)NNODES * 32 + (size_t)node * 32 + lane] = fmaf(di, al, bls[lane]);
}

// ---------------- launch ----------------
extern "C" void kernel_launch(void* const* d_in, const int* in_sizes, int n_in,
                              void* d_out, int out_size) {
    (void)in_sizes; (void)n_in; (void)out_size;

    const float* x   = (const float*)d_in[0];
    const int*   ei  = (const int*)d_in[1];
    const float* W1  = (const float*)d_in[2];
    const float* b1  = (const float*)d_in[3];
    const float* Wr1 = (const float*)d_in[4];
    const float* W2  = (const float*)d_in[5];
    const float* b2  = (const float*)d_in[6];
    const float* Wr2 = (const float*)d_in[7];
    const float* Wmu = (const float*)d_in[8];
    const float* bmu = (const float*)d_in[9];
    const float* Wls = (const float*)d_in[10];
    const float* bls = (const float*)d_in[11];
    float* out = (float*)d_out;

    const int* src = ei;
    const int* dst = ei + NEDGES;

    // dynamic smem sizes: (2*128 + 2*NW) * (K+8) * sizeof(bf16)
    constexpr int SM1 = (256 + 2 * 192) * (F_IN + 8) * 2;   // 174080
    constexpr int SM2 = (256 + 2 * 128) * (F_L1 + 8) * 2;   // 106496
    constexpr int SM3 = (256 + 2 * 64)  * (F_L2 + 8) * 2;   //  55296

    static float *p_y = nullptr, *p_r = nullptr, *p_h1 = nullptr, *p_h2 = nullptr,
                 *p_m = nullptr, *p_l = nullptr, *p_dis = nullptr;
    if (!p_y) {  // one-time address lookup + smem opt-in (no allocations, no stream ops)
        cudaGetSymbolAddress((void**)&p_y,  g_y);
        cudaGetSymbolAddress((void**)&p_r,  g_r);
        cudaGetSymbolAddress((void**)&p_h1, g_h1);
        cudaGetSymbolAddress((void**)&p_h2, g_h2);
        cudaGetSymbolAddress((void**)&p_m,  g_m);
        cudaGetSymbolAddress((void**)&p_l,  g_l);
        cudaGetSymbolAddress((void**)&p_dis, g_dis);
        cudaFuncSetAttribute(mma_gemm_kernel<F_IN, 192, false>,
                             cudaFuncAttributeMaxDynamicSharedMemorySize, SM1);
        cudaFuncSetAttribute(mma_gemm_kernel<F_L1, 128, false>,
                             cudaFuncAttributeMaxDynamicSharedMemorySize, SM2);
        cudaFuncSetAttribute(mma_gemm_kernel<F_L2, 64, true>,
                             cudaFuncAttributeMaxDynamicSharedMemorySize, SM3);
    }

    constexpr int TB = 256;
    const int gridN  = (NNODES + TB - 1) / TB;
    const int gridE  = (NEDGES + TB - 1) / TB;
    const int gridGM = (NNODES + 127) / 128;                 // GEMM row blocks
    const int gridGA = ((size_t)NNODES * 32 + TB - 1) / TB;  // 1 warp / node

    // 1) CSR + normalization factors
    init_deg_kernel<<<gridN, TB>>>();
    count_deg_kernel<<<gridE, TB>>>(dst);
    scan_kernel<<<1, 1024>>>();
    fill_csr_kernel<<<gridE, TB>>>(src, dst);

    // 2) layer 1: [y|r] = x @ [W1|Wr1], gather+relu
    mma_gemm_kernel<F_IN, 192, false><<<gridGM, TB, SM1>>>(x, W1, Wr1, nullptr, p_y, p_r);
    layer_gather_kernel<F_L1><<<gridGA, TB>>>(p_y, p_r, b1, p_h1);

    // 3) layer 2
    mma_gemm_kernel<F_L1, 128, false><<<gridGM, TB, SM2>>>(p_h1, W2, Wr2, nullptr, p_y, p_r);
    layer_gather_kernel<F_L2><<<gridGA, TB>>>(p_y, p_r, b2, p_h2);

    // 4) GCN heads: one fused GEMM (dis-prescaled rows) + one fused gather
    mma_gemm_kernel<F_L2, 64, true><<<gridGM, TB, SM3>>>(p_h2, Wmu, Wls, p_dis, p_m, p_l);
    head_gather2_kernel<<<gridGA, TB>>>(p_m, p_l, bmu, bls, out);
}

// round 14
// speedup vs baseline: 1.8115x; 1.7936x over previous
#include <cuda_runtime.h>
#include <cuda_bf16.h>
#include <cstdint>

// Problem constants (fixed by the reference)
constexpr int NNODES = 100000;
constexpr int NEDGES = 600000;
constexpr int F_IN  = 128;
constexpr int F_L1  = 96;
constexpr int F_L2  = 64;
constexpr int F_OUT = 32;

constexpr int SCAN_BLK = 256;
constexpr int SCAN_NBLK = (NNODES + SCAN_BLK - 1) / SCAN_BLK;   // 391

// ---------------- scratch (device globals; no allocations allowed) ----------
__device__ float g_y [(size_t)NNODES * F_L1];   // neighbor-branch GEMM out (96 then 64)
__device__ float g_r [(size_t)NNODES * F_L1];   // root-branch GEMM out
__device__ float g_h1[(size_t)NNODES * F_L1];   // layer-1 activations
__device__ float g_h2[(size_t)NNODES * F_L2];   // layer-2 activations
__device__ float g_ml[(size_t)NNODES * 64];     // heads pre-agg, interleaved [mu(32)|ls(32)]

__device__ float g_dinv[NNODES];
__device__ float g_dis [NNODES];
__device__ int   g_degcnt[NNODES];
__device__ int   g_rowstart[NNODES + 1];
__device__ int   g_pos[NNODES];
__device__ int   g_csr[NEDGES];
__device__ int   g_blocksum[SCAN_NBLK + 1];
__device__ int   g_blockbase[SCAN_NBLK + 1];

// ---------------- CSR build ----------------
__global__ void count_deg_kernel(const int* __restrict__ dst) {
    int e = blockIdx.x * blockDim.x + threadIdx.x;
    if (e < NEDGES) atomicAdd(&g_degcnt[dst[e]], 1);
}

// 3-stage parallel exclusive scan over degcnt
__global__ void scan_partial_kernel() {
    int i = blockIdx.x * SCAN_BLK + threadIdx.x;
    int v = (i < NNODES) ? g_degcnt[i] : 0;
#pragma unroll
    for (int o = 16; o; o >>= 1) v += __shfl_down_sync(0xffffffffu, v, o);
    __shared__ int ws[8];
    if ((threadIdx.x & 31) == 0) ws[threadIdx.x >> 5] = v;
    __syncthreads();
    if (threadIdx.x == 0) {
        int s = 0;
#pragma unroll
        for (int k = 0; k < 8; k++) s += ws[k];
        g_blocksum[blockIdx.x] = s;
    }
}

__global__ void scan_tops_kernel() {
    __shared__ int sh[512];
    const int t = threadIdx.x;
    int v = (t < SCAN_NBLK) ? g_blocksum[t] : 0;
    sh[t] = v;
    __syncthreads();
    for (int off = 1; off < 512; off <<= 1) {
        int a = (t >= off) ? sh[t - off] : 0;
        __syncthreads();
        sh[t] += a;
        __syncthreads();
    }
    if (t < SCAN_NBLK) g_blockbase[t] = (t ? sh[t - 1] : 0);
    if (t == SCAN_NBLK - 1) g_rowstart[NNODES] = sh[t];     // == NEDGES
}

__global__ void scan_final_kernel() {
    const int i = blockIdx.x * SCAN_BLK + threadIdx.x;
    const int lane = threadIdx.x & 31, w = threadIdx.x >> 5;
    int d = (i < NNODES) ? g_degcnt[i] : 0;
    int x = d;
#pragma unroll
    for (int o = 1; o < 32; o <<= 1) {
        int y = __shfl_up_sync(0xffffffffu, x, o);
        if (lane >= o) x += y;
    }
    __shared__ int wsum[8];
    if (lane == 31) wsum[w] = x;
    __syncthreads();
    if (threadIdx.x == 0) {
        int run = 0;
#pragma unroll
        for (int k = 0; k < 8; k++) { int t = wsum[k]; wsum[k] = run; run += t; }
    }
    __syncthreads();
    if (i < NNODES) {
        int excl = (x - d) + wsum[w] + g_blockbase[blockIdx.x];
        g_rowstart[i] = excl;
        g_pos[i] = excl;
        float deg = (float)(d + 1);                         // + self loop
        g_dinv[i] = 1.0f / deg;
        g_dis[i]  = rsqrtf(deg);
    }
}

__global__ void fill_csr_kernel(const int* __restrict__ src, const int* __restrict__ dst) {
    int e = blockIdx.x * blockDim.x + threadIdx.x;
    if (e < NEDGES) {
        int d = dst[e];
        int idx = atomicAdd(&g_pos[d], 1);
        g_csr[idx] = src[e];
    }
}

// ---------------- tensor-core GEMM (bf16 hi/lo 3-MMA split) -----------------
// C[N rows, Nw cols] = A[rows, K] @ [B0 | B1]   (B0,B1 each [K, Nw/2] row-major)
// Columns [0, Nw/2) -> Cy, columns [Nw/2, Nw) -> Cr (leading dim ldc). Optional row scale.
// Block: 256 threads = 8 warps (4 m-groups x 2 n-groups), BM=128, full K resident.

__device__ __forceinline__ void mma_bf16(float* c, uint32_t a0, uint32_t a1,
                                         uint32_t a2, uint32_t a3,
                                         uint32_t b0, uint32_t b1) {
    asm volatile(
        "mma.sync.aligned.m16n8k16.row.col.f32.bf16.bf16.f32 "
        "{%0,%1,%2,%3}, {%4,%5,%6,%7}, {%8,%9}, {%0,%1,%2,%3};\n"
        : "+f"(c[0]), "+f"(c[1]), "+f"(c[2]), "+f"(c[3])
        : "r"(a0), "r"(a1), "r"(a2), "r"(a3), "r"(b0), "r"(b1));
}

template <int K, int NW, bool ROWSCALE>
__global__ __launch_bounds__(256, 1)
void mma_gemm_kernel(const float* __restrict__ A,
                     const float* __restrict__ B0, const float* __restrict__ B1,
                     const float* __restrict__ rowscale,
                     float* __restrict__ Cy, float* __restrict__ Cr, int ldc) {
    constexpr int KP = K + 8;          // pad: word-stride/row = (K+8)/2 ≡ 4 (mod 32)
    constexpr int HN = NW / 2;
    constexpr int NT = HN / 8;         // n8 tiles per warp
    static_assert(K % 16 == 0 && HN % 8 == 0, "");

    extern __shared__ __nv_bfloat16 sm[];
    __nv_bfloat16* Ah = sm;
    __nv_bfloat16* Al = Ah + 128 * KP;
    __nv_bfloat16* Bh = Al + 128 * KP;   // B stored transposed: [n][k]
    __nv_bfloat16* Bl = Bh + NW * KP;

    const int tid  = threadIdx.x;
    const int row0 = blockIdx.x * 128;

    // ---- load A tile (128 x K), split into hi/lo bf16 ----
    for (int idx = tid; idx < 128 * (K / 4); idx += 256) {
        int row = idx / (K / 4);
        int kq  = (idx % (K / 4)) * 4;
        float4 v = make_float4(0.f, 0.f, 0.f, 0.f);
        if (row0 + row < NNODES)
            v = *reinterpret_cast<const float4*>(A + (size_t)(row0 + row) * K + kq);
        float f[4] = {v.x, v.y, v.z, v.w};
        __nv_bfloat16 h[4], l[4];
#pragma unroll
        for (int q = 0; q < 4; q++) {
            h[q] = __float2bfloat16(f[q]);
            l[q] = __float2bfloat16(f[q] - __bfloat162float(h[q]));
        }
        *reinterpret_cast<uint2*>(&Ah[row * KP + kq]) = *reinterpret_cast<uint2*>(h);
        *reinterpret_cast<uint2*>(&Al[row * KP + kq]) = *reinterpret_cast<uint2*>(l);
    }

    // ---- load [B0|B1] transposed (NW x K), hi/lo, u32-vectorized stores ----
    for (int idx = tid; idx < NW * (K / 2); idx += 256) {
        int kk = idx / NW;           // k pair index
        int n  = idx % NW;           // coalesced over lanes
        int k  = kk * 2;
        float w0, w1;
        if (n < HN) { w0 = B0[(size_t)k * HN + n];        w1 = B0[(size_t)(k + 1) * HN + n]; }
        else        { w0 = B1[(size_t)k * HN + (n - HN)]; w1 = B1[(size_t)(k + 1) * HN + (n - HN)]; }
        __nv_bfloat16 h[2], l[2];
        h[0] = __float2bfloat16(w0); l[0] = __float2bfloat16(w0 - __bfloat162float(h[0]));
        h[1] = __float2bfloat16(w1); l[1] = __float2bfloat16(w1 - __bfloat162float(h[1]));
        *reinterpret_cast<uint32_t*>(&Bh[n * KP + k]) = *reinterpret_cast<uint32_t*>(h);
        *reinterpret_cast<uint32_t*>(&Bl[n * KP + k]) = *reinterpret_cast<uint32_t*>(l);
    }
    __syncthreads();

    // ---- warp tiling ----
    const int w    = tid >> 5;
    const int lane = tid & 31;
    const int wm   = w & 3;          // 4 row groups of 32
    const int wn   = w >> 2;         // 2 col groups of HN
    const int g    = lane >> 2;      // 0..7
    const int t    = lane & 3;       // 0..3

    float acc[2][NT][4];
#pragma unroll
    for (int mt = 0; mt < 2; mt++)
#pragma unroll
        for (int nt = 0; nt < NT; nt++)
#pragma unroll
            for (int q = 0; q < 4; q++) acc[mt][nt][q] = 0.f;

    for (int k0 = 0; k0 < K; k0 += 16) {
        uint32_t ah[2][4], al[2][4];
#pragma unroll
        for (int mt = 0; mt < 2; mt++) {
            int r = wm * 32 + mt * 16 + g;
            const __nv_bfloat16* ph = Ah + r * KP + k0;
            const __nv_bfloat16* pl = Al + r * KP + k0;
            ah[mt][0] = *reinterpret_cast<const uint32_t*>(ph + 2 * t);
            ah[mt][1] = *reinterpret_cast<const uint32_t*>(ph + 8 * KP + 2 * t);
            ah[mt][2] = *reinterpret_cast<const uint32_t*>(ph + 2 * t + 8);
            ah[mt][3] = *reinterpret_cast<const uint32_t*>(ph + 8 * KP + 2 * t + 8);
            al[mt][0] = *reinterpret_cast<const uint32_t*>(pl + 2 * t);
            al[mt][1] = *reinterpret_cast<const uint32_t*>(pl + 8 * KP + 2 * t);
            al[mt][2] = *reinterpret_cast<const uint32_t*>(pl + 2 * t + 8);
            al[mt][3] = *reinterpret_cast<const uint32_t*>(pl + 8 * KP + 2 * t + 8);
        }
#pragma unroll
        for (int nt = 0; nt < NT; nt++) {
            int n = wn * HN + nt * 8 + g;
            const __nv_bfloat16* qh = Bh + n * KP + k0;
            const __nv_bfloat16* ql = Bl + n * KP + k0;
            uint32_t bh0 = *reinterpret_cast<const uint32_t*>(qh + 2 * t);
            uint32_t bh1 = *reinterpret_cast<const uint32_t*>(qh + 2 * t + 8);
            uint32_t bl0 = *reinterpret_cast<const uint32_t*>(ql + 2 * t);
            uint32_t bl1 = *reinterpret_cast<const uint32_t*>(ql + 2 * t + 8);
#pragma unroll
            for (int mt = 0; mt < 2; mt++) {
                mma_bf16(acc[mt][nt], ah[mt][0], ah[mt][1], ah[mt][2], ah[mt][3], bh0, bh1);
                mma_bf16(acc[mt][nt], ah[mt][0], ah[mt][1], ah[mt][2], ah[mt][3], bl0, bl1);
                mma_bf16(acc[mt][nt], al[mt][0], al[mt][1], al[mt][2], al[mt][3], bh0, bh1);
            }
        }
    }

    // ---- epilogue ----
    float* Cout = wn ? Cr : Cy;
#pragma unroll
    for (int mt = 0; mt < 2; mt++) {
        int r0 = row0 + wm * 32 + mt * 16 + g;
        int r1 = r0 + 8;
        float s0 = 1.f, s1 = 1.f;
        if (ROWSCALE) {
            if (r0 < NNODES) s0 = rowscale[r0];
            if (r1 < NNODES) s1 = rowscale[r1];
        }
#pragma unroll
        for (int nt = 0; nt < NT; nt++) {
            int c = nt * 8 + 2 * t;
            if (r0 < NNODES) {
                float2 v = make_float2(acc[mt][nt][0] * s0, acc[mt][nt][1] * s0);
                *reinterpret_cast<float2*>(&Cout[(size_t)r0 * ldc + c]) = v;
            }
            if (r1 < NNODES) {
                float2 v = make_float2(acc[mt][nt][2] * s1, acc[mt][nt][3] * s1);
                *reinterpret_cast<float2*>(&Cout[(size_t)r1 * ldc + c]) = v;
            }
        }
    }
}

// ---------------- aggregation (gather, atomic-free, 4x pipelined) ----------------
// ClusterGCN layer: out = relu( dinv[i]*(y[i] + sum_{j->i} y[j]) + r[i] + b )
template <int F>
__launch_bounds__(256)
__global__ void layer_gather_kernel(const float* __restrict__ y, const float* __restrict__ r,
                                    const float* __restrict__ bias, float* __restrict__ out) {
    const int node = (blockIdx.x * blockDim.x + threadIdx.x) >> 5;
    const int lane = threadIdx.x & 31;
    if (node >= NNODES) return;
    constexpr int C = F / 32;

    float acc[C];
    const float* yi = y + (size_t)node * F + lane;
#pragma unroll
    for (int c = 0; c < C; c++) acc[c] = __ldg(yi + 32 * c);   // self loop

    const int s = g_rowstart[node];
    const int e = g_rowstart[node + 1];
    int p = s;
    for (; p + 4 <= e; p += 4) {
        int i0 = __ldg(&g_csr[p]);
        int i1 = __ldg(&g_csr[p + 1]);
        int i2 = __ldg(&g_csr[p + 2]);
        int i3 = __ldg(&g_csr[p + 3]);
        const float* p0 = y + (size_t)i0 * F + lane;
        const float* p1 = y + (size_t)i1 * F + lane;
        const float* p2 = y + (size_t)i2 * F + lane;
        const float* p3 = y + (size_t)i3 * F + lane;
        float v0[C], v1[C], v2[C], v3[C];
#pragma unroll
        for (int c = 0; c < C; c++) {
            v0[c] = __ldg(p0 + 32 * c);
            v1[c] = __ldg(p1 + 32 * c);
            v2[c] = __ldg(p2 + 32 * c);
            v3[c] = __ldg(p3 + 32 * c);
        }
#pragma unroll
        for (int c = 0; c < C; c++) acc[c] += (v0[c] + v1[c]) + (v2[c] + v3[c]);
    }
    for (; p < e; p++) {
        int j = __ldg(&g_csr[p]);
        const float* pj = y + (size_t)j * F + lane;
#pragma unroll
        for (int c = 0; c < C; c++) acc[c] += __ldg(pj + 32 * c);
    }

    const float di = g_dinv[node];
#pragma unroll
    for (int c = 0; c < C; c++) {
        int f = lane + 32 * c;
        float v = fmaf(di, acc[c], __ldg(r + (size_t)node * F + f) + __ldg(bias + f));
        out[(size_t)node * F + f] = fmaxf(v, 0.f);
    }
}

// Both GCN heads, interleaved [mu|ls] 64-wide buffer (dis[src]-prescaled rows):
// out = dis[i]*(ml[i] + sum_{j->i} ml[j]) + b
__launch_bounds__(256)
__global__ void head_gather2_kernel(const float* __restrict__ ml,
                                    const float* __restrict__ bmu, const float* __restrict__ bls,
                                    float* __restrict__ out) {
    const int node = (blockIdx.x * blockDim.x + threadIdx.x) >> 5;
    const int lane = threadIdx.x & 31;
    if (node >= NNODES) return;

    float a0 = __ldg(ml + (size_t)node * 64 + lane);
    float a1 = __ldg(ml + (size_t)node * 64 + 32 + lane);

    const int s = g_rowstart[node];
    const int e = g_rowstart[node + 1];
    int p = s;
    for (; p + 4 <= e; p += 4) {
        int i0 = __ldg(&g_csr[p]);
        int i1 = __ldg(&g_csr[p + 1]);
        int i2 = __ldg(&g_csr[p + 2]);
        int i3 = __ldg(&g_csr[p + 3]);
        const float* p0 = ml + (size_t)i0 * 64 + lane;
        const float* p1 = ml + (size_t)i1 * 64 + lane;
        const float* p2 = ml + (size_t)i2 * 64 + lane;
        const float* p3 = ml + (size_t)i3 * 64 + lane;
        float m0 = __ldg(p0),      m1 = __ldg(p1),      m2 = __ldg(p2),      m3 = __ldg(p3);
        float l0 = __ldg(p0 + 32), l1 = __ldg(p1 + 32), l2 = __ldg(p2 + 32), l3 = __ldg(p3 + 32);
        a0 += (m0 + m1) + (m2 + m3);
        a1 += (l0 + l1) + (l2 + l3);
    }
    for (; p < e; p++) {
        int j = __ldg(&g_csr[p]);
        a0 += __ldg(ml + (size_t)j * 64 + lane);
        a1 += __ldg(ml + (size_t)j * 64 + 32 + lane);
    }

    const float di = g_dis[node];
    out[(size_t)node * 32 + lane] = fmaf(di, a0, __ldg(bmu + lane));
    out[(size_t)NNODES * 32 + (size_t)node * 32 + lane] = fmaf(di, a1, __ldg(bls + lane));
}

// ---------------- launch ----------------
extern "C" void kernel_launch(void* const* d_in, const int* in_sizes, int n_in,
                              void* d_out, int out_size) {
    (void)in_sizes; (void)n_in; (void)out_size;

    const float* x   = (const float*)d_in[0];
    const int*   ei  = (const int*)d_in[1];
    const float* W1  = (const float*)d_in[2];
    const float* b1  = (const float*)d_in[3];
    const float* Wr1 = (const float*)d_in[4];
    const float* W2  = (const float*)d_in[5];
    const float* b2  = (const float*)d_in[6];
    const float* Wr2 = (const float*)d_in[7];
    const float* Wmu = (const float*)d_in[8];
    const float* bmu = (const float*)d_in[9];
    const float* Wls = (const float*)d_in[10];
    const float* bls = (const float*)d_in[11];
    float* out = (float*)d_out;

    const int* src = ei;
    const int* dst = ei + NEDGES;

    // dynamic smem sizes: (2*128 + 2*NW) * (K+8) * sizeof(bf16)
    constexpr int SM1 = (256 + 2 * 192) * (F_IN + 8) * 2;   // 174080
    constexpr int SM2 = (256 + 2 * 128) * (F_L1 + 8) * 2;   // 106496
    constexpr int SM3 = (256 + 2 * 64)  * (F_L2 + 8) * 2;   //  55296

    static float *p_y = nullptr, *p_r = nullptr, *p_h1 = nullptr, *p_h2 = nullptr,
                 *p_ml = nullptr, *p_dis = nullptr;
    static int *p_degcnt = nullptr;
    if (!p_y) {  // one-time address lookup + smem opt-in (no allocations, no stream ops)
        cudaGetSymbolAddress((void**)&p_y,  g_y);
        cudaGetSymbolAddress((void**)&p_r,  g_r);
        cudaGetSymbolAddress((void**)&p_h1, g_h1);
        cudaGetSymbolAddress((void**)&p_h2, g_h2);
        cudaGetSymbolAddress((void**)&p_ml, g_ml);
        cudaGetSymbolAddress((void**)&p_dis, g_dis);
        cudaGetSymbolAddress((void**)&p_degcnt, g_degcnt);
        cudaFuncSetAttribute(mma_gemm_kernel<F_IN, 192, false>,
                             cudaFuncAttributeMaxDynamicSharedMemorySize, SM1);
        cudaFuncSetAttribute(mma_gemm_kernel<F_L1, 128, false>,
                             cudaFuncAttributeMaxDynamicSharedMemorySize, SM2);
        cudaFuncSetAttribute(mma_gemm_kernel<F_L2, 64, true>,
                             cudaFuncAttributeMaxDynamicSharedMemorySize, SM3);
    }

    constexpr int TB = 256;
    const int gridE  = (NEDGES + TB - 1) / TB;
    const int gridGM = (NNODES + 127) / 128;                 // GEMM row blocks
    const int gridGA = ((size_t)NNODES * 32 + TB - 1) / TB;  // 1 warp / node

    // 1) CSR + normalization factors (parallel 3-stage scan)
    cudaMemsetAsync(p_degcnt, 0, NNODES * sizeof(int));
    count_deg_kernel<<<gridE, TB>>>(dst);
    scan_partial_kernel<<<SCAN_NBLK, SCAN_BLK>>>();
    scan_tops_kernel<<<1, 512>>>();
    scan_final_kernel<<<SCAN_NBLK, SCAN_BLK>>>();
    fill_csr_kernel<<<gridE, TB>>>(src, dst);

    // 2) layer 1: [y|r] = x @ [W1|Wr1], gather+relu
    mma_gemm_kernel<F_IN, 192, false><<<gridGM, TB, SM1>>>(x, W1, Wr1, nullptr, p_y, p_r, 96);
    layer_gather_kernel<F_L1><<<gridGA, TB>>>(p_y, p_r, b1, p_h1);

    // 3) layer 2
    mma_gemm_kernel<F_L1, 128, false><<<gridGM, TB, SM2>>>(p_h1, W2, Wr2, nullptr, p_y, p_r, 64);
    layer_gather_kernel<F_L2><<<gridGA, TB>>>(p_y, p_r, b2, p_h2);

    // 4) GCN heads: one fused GEMM into interleaved [mu|ls] buffer + one fused gather
    mma_gemm_kernel<F_L2, 64, true><<<gridGM, TB, SM3>>>(p_h2, Wmu, Wls, p_dis, p_ml, p_ml + 32, 64);
    head_gather2_kernel<<<gridGA, TB>>>(p_ml, bmu, bls, out);
}

// round 17
// speedup vs baseline: 1.8127x; 1.0007x over previous
#include <cuda_runtime.h>
#include <cuda_bf16.h>
#include <cstdint>

// Problem constants (fixed by the reference)
constexpr int NNODES = 100000;
constexpr int NEDGES = 600000;
constexpr int F_IN  = 128;
constexpr int F_L1  = 96;
constexpr int F_L2  = 64;
constexpr int F_OUT = 32;

constexpr int SCAN_BLK = 256;
constexpr int SCAN_NBLK = (NNODES + SCAN_BLK - 1) / SCAN_BLK;   // 391

// ---------------- scratch (device globals; no allocations allowed) ----------
__device__ float g_y [(size_t)NNODES * F_L1];   // neighbor-branch GEMM out (96 then 64)
__device__ float g_r [(size_t)NNODES * F_L1];   // root-branch GEMM out
__device__ float g_h1[(size_t)NNODES * F_L1];   // layer-1 activations
__device__ float g_h2[(size_t)NNODES * F_L2];   // layer-2 activations
__device__ float g_ml[(size_t)NNODES * 64];     // heads pre-agg, interleaved [mu(32)|ls(32)]

__device__ float g_dinv[NNODES];
__device__ float g_dis [NNODES];
__device__ int   g_degcnt[NNODES];
__device__ int   g_rowstart[NNODES + 1];
__device__ int   g_pos[NNODES];
__device__ int   g_csr[NEDGES];
__device__ int   g_blocksum[SCAN_NBLK + 1];
__device__ int   g_blockbase[SCAN_NBLK + 1];

// ---------------- CSR build ----------------
__global__ void count_deg_kernel(const int* __restrict__ dst) {
    int e = blockIdx.x * blockDim.x + threadIdx.x;
    if (e < NEDGES) atomicAdd(&g_degcnt[dst[e]], 1);
}

// 3-stage parallel exclusive scan over degcnt
__global__ void scan_partial_kernel() {
    int i = blockIdx.x * SCAN_BLK + threadIdx.x;
    int v = (i < NNODES) ? g_degcnt[i] : 0;
#pragma unroll
    for (int o = 16; o; o >>= 1) v += __shfl_down_sync(0xffffffffu, v, o);
    __shared__ int ws[8];
    if ((threadIdx.x & 31) == 0) ws[threadIdx.x >> 5] = v;
    __syncthreads();
    if (threadIdx.x == 0) {
        int s = 0;
#pragma unroll
        for (int k = 0; k < 8; k++) s += ws[k];
        g_blocksum[blockIdx.x] = s;
    }
}

__global__ void scan_tops_kernel() {
    __shared__ int sh[512];
    const int t = threadIdx.x;
    int v = (t < SCAN_NBLK) ? g_blocksum[t] : 0;
    sh[t] = v;
    __syncthreads();
    for (int off = 1; off < 512; off <<= 1) {
        int a = (t >= off) ? sh[t - off] : 0;
        __syncthreads();
        sh[t] += a;
        __syncthreads();
    }
    if (t < SCAN_NBLK) g_blockbase[t] = (t ? sh[t - 1] : 0);
    if (t == SCAN_NBLK - 1) g_rowstart[NNODES] = sh[t];     // == NEDGES
}

__global__ void scan_final_kernel() {
    const int i = blockIdx.x * SCAN_BLK + threadIdx.x;
    const int lane = threadIdx.x & 31, w = threadIdx.x >> 5;
    int d = (i < NNODES) ? g_degcnt[i] : 0;
    int x = d;
#pragma unroll
    for (int o = 1; o < 32; o <<= 1) {
        int y = __shfl_up_sync(0xffffffffu, x, o);
        if (lane >= o) x += y;
    }
    __shared__ int wsum[8];
    if (lane == 31) wsum[w] = x;
    __syncthreads();
    if (threadIdx.x == 0) {
        int run = 0;
#pragma unroll
        for (int k = 0; k < 8; k++) { int t = wsum[k]; wsum[k] = run; run += t; }
    }
    __syncthreads();
    if (i < NNODES) {
        int excl = (x - d) + wsum[w] + g_blockbase[blockIdx.x];
        g_rowstart[i] = excl;
        g_pos[i] = excl;
        float deg = (float)(d + 1);                         // + self loop
        g_dinv[i] = 1.0f / deg;
        g_dis[i]  = rsqrtf(deg);
    }
}

__global__ void fill_csr_kernel(const int* __restrict__ src, const int* __restrict__ dst) {
    int e = blockIdx.x * blockDim.x + threadIdx.x;
    if (e < NEDGES) {
        int d = dst[e];
        int idx = atomicAdd(&g_pos[d], 1);
        g_csr[idx] = src[e];
    }
}

// ---------------- tensor-core GEMM (bf16 hi/lo 3-MMA split) -----------------
// C[N rows, Nw cols] = A[rows, K] @ [B0 | B1]   (B0,B1 each [K, Nw/2] row-major)
// Columns [0, Nw/2) -> Cy, columns [Nw/2, Nw) -> Cr (leading dim ldc). Optional row scale.
// Block: 256 threads = 8 warps (4 m-groups x 2 n-groups), BM=128, full K resident.

__device__ __forceinline__ void mma_bf16(float* c, uint32_t a0, uint32_t a1,
                                         uint32_t a2, uint32_t a3,
                                         uint32_t b0, uint32_t b1) {
    asm volatile(
        "mma.sync.aligned.m16n8k16.row.col.f32.bf16.bf16.f32 "
        "{%0,%1,%2,%3}, {%4,%5,%6,%7}, {%8,%9}, {%0,%1,%2,%3};\n"
        : "+f"(c[0]), "+f"(c[1]), "+f"(c[2]), "+f"(c[3])
        : "r"(a0), "r"(a1), "r"(a2), "r"(a3), "r"(b0), "r"(b1));
}

template <int K, int NW, bool ROWSCALE>
__global__ __launch_bounds__(256, 1)
void mma_gemm_kernel(const float* __restrict__ A,
                     const float* __restrict__ B0, const float* __restrict__ B1,
                     const float* __restrict__ rowscale,
                     float* __restrict__ Cy, float* __restrict__ Cr, int ldc) {
    constexpr int KP = K + 8;          // pad: word-stride/row = (K+8)/2 ≡ 4 (mod 32)
    constexpr int HN = NW / 2;
    constexpr int NT = HN / 8;         // n8 tiles per warp
    static_assert(K % 16 == 0 && HN % 8 == 0, "");

    extern __shared__ __nv_bfloat16 sm[];
    __nv_bfloat16* Ah = sm;
    __nv_bfloat16* Al = Ah + 128 * KP;
    __nv_bfloat16* Bh = Al + 128 * KP;   // B stored transposed: [n][k]
    __nv_bfloat16* Bl = Bh + NW * KP;

    const int tid  = threadIdx.x;
    const int row0 = blockIdx.x * 128;

    // ---- load A tile (128 x K), split into hi/lo bf16 ----
    for (int idx = tid; idx < 128 * (K / 4); idx += 256) {
        int row = idx / (K / 4);
        int kq  = (idx % (K / 4)) * 4;
        float4 v = make_float4(0.f, 0.f, 0.f, 0.f);
        if (row0 + row < NNODES)
            v = *reinterpret_cast<const float4*>(A + (size_t)(row0 + row) * K + kq);
        float f[4] = {v.x, v.y, v.z, v.w};
        __nv_bfloat16 h[4], l[4];
#pragma unroll
        for (int q = 0; q < 4; q++) {
            h[q] = __float2bfloat16(f[q]);
            l[q] = __float2bfloat16(f[q] - __bfloat162float(h[q]));
        }
        *reinterpret_cast<uint2*>(&Ah[row * KP + kq]) = *reinterpret_cast<uint2*>(h);
        *reinterpret_cast<uint2*>(&Al[row * KP + kq]) = *reinterpret_cast<uint2*>(l);
    }

    // ---- load [B0|B1] transposed (NW x K), hi/lo, u32-vectorized stores ----
    for (int idx = tid; idx < NW * (K / 2); idx += 256) {
        int kk = idx / NW;           // k pair index
        int n  = idx % NW;           // coalesced over lanes
        int k  = kk * 2;
        float w0, w1;
        if (n < HN) { w0 = B0[(size_t)k * HN + n];        w1 = B0[(size_t)(k + 1) * HN + n]; }
        else        { w0 = B1[(size_t)k * HN + (n - HN)]; w1 = B1[(size_t)(k + 1) * HN + (n - HN)]; }
        __nv_bfloat16 h[2], l[2];
        h[0] = __float2bfloat16(w0); l[0] = __float2bfloat16(w0 - __bfloat162float(h[0]));
        h[1] = __float2bfloat16(w1); l[1] = __float2bfloat16(w1 - __bfloat162float(h[1]));
        *reinterpret_cast<uint32_t*>(&Bh[n * KP + k]) = *reinterpret_cast<uint32_t*>(h);
        *reinterpret_cast<uint32_t*>(&Bl[n * KP + k]) = *reinterpret_cast<uint32_t*>(l);
    }
    __syncthreads();

    // ---- warp tiling ----
    const int w    = tid >> 5;
    const int lane = tid & 31;
    const int wm   = w & 3;          // 4 row groups of 32
    const int wn   = w >> 2;         // 2 col groups of HN
    const int g    = lane >> 2;      // 0..7
    const int t    = lane & 3;       // 0..3

    float acc[2][NT][4];
#pragma unroll
    for (int mt = 0; mt < 2; mt++)
#pragma unroll
        for (int nt = 0; nt < NT; nt++)
#pragma unroll
            for (int q = 0; q < 4; q++) acc[mt][nt][q] = 0.f;

    for (int k0 = 0; k0 < K; k0 += 16) {
        uint32_t ah[2][4], al[2][4];
#pragma unroll
        for (int mt = 0; mt < 2; mt++) {
            int r = wm * 32 + mt * 16 + g;
            const __nv_bfloat16* ph = Ah + r * KP + k0;
            const __nv_bfloat16* pl = Al + r * KP + k0;
            ah[mt][0] = *reinterpret_cast<const uint32_t*>(ph + 2 * t);
            ah[mt][1] = *reinterpret_cast<const uint32_t*>(ph + 8 * KP + 2 * t);
            ah[mt][2] = *reinterpret_cast<const uint32_t*>(ph + 2 * t + 8);
            ah[mt][3] = *reinterpret_cast<const uint32_t*>(ph + 8 * KP + 2 * t + 8);
            al[mt][0] = *reinterpret_cast<const uint32_t*>(pl + 2 * t);
            al[mt][1] = *reinterpret_cast<const uint32_t*>(pl + 8 * KP + 2 * t);
            al[mt][2] = *reinterpret_cast<const uint32_t*>(pl + 2 * t + 8);
            al[mt][3] = *reinterpret_cast<const uint32_t*>(pl + 8 * KP + 2 * t + 8);
        }
#pragma unroll
        for (int nt = 0; nt < NT; nt++) {
            int n = wn * HN + nt * 8 + g;
            const __nv_bfloat16* qh = Bh + n * KP + k0;
            const __nv_bfloat16* ql = Bl + n * KP + k0;
            uint32_t bh0 = *reinterpret_cast<const uint32_t*>(qh + 2 * t);
            uint32_t bh1 = *reinterpret_cast<const uint32_t*>(qh + 2 * t + 8);
            uint32_t bl0 = *reinterpret_cast<const uint32_t*>(ql + 2 * t);
            uint32_t bl1 = *reinterpret_cast<const uint32_t*>(ql + 2 * t + 8);
#pragma unroll
            for (int mt = 0; mt < 2; mt++) {
                mma_bf16(acc[mt][nt], ah[mt][0], ah[mt][1], ah[mt][2], ah[mt][3], bh0, bh1);
                mma_bf16(acc[mt][nt], ah[mt][0], ah[mt][1], ah[mt][2], ah[mt][3], bl0, bl1);
                mma_bf16(acc[mt][nt], al[mt][0], al[mt][1], al[mt][2], al[mt][3], bh0, bh1);
            }
        }
    }

    // ---- epilogue ----
    float* Cout = wn ? Cr : Cy;
#pragma unroll
    for (int mt = 0; mt < 2; mt++) {
        int r0 = row0 + wm * 32 + mt * 16 + g;
        int r1 = r0 + 8;
        float s0 = 1.f, s1 = 1.f;
        if (ROWSCALE) {
            if (r0 < NNODES) s0 = rowscale[r0];
            if (r1 < NNODES) s1 = rowscale[r1];
        }
#pragma unroll
        for (int nt = 0; nt < NT; nt++) {
            int c = nt * 8 + 2 * t;
            if (r0 < NNODES) {
                float2 v = make_float2(acc[mt][nt][0] * s0, acc[mt][nt][1] * s0);
                *reinterpret_cast<float2*>(&Cout[(size_t)r0 * ldc + c]) = v;
            }
            if (r1 < NNODES) {
                float2 v = make_float2(acc[mt][nt][2] * s1, acc[mt][nt][3] * s1);
                *reinterpret_cast<float2*>(&Cout[(size_t)r1 * ldc + c]) = v;
            }
        }
    }
}

// ---------------- aggregation (gather, atomic-free, 4x pipelined) ----------------
// ClusterGCN layer: out = relu( dinv[i]*(y[i] + sum_{j->i} y[j]) + r[i] + b )
template <int F>
__launch_bounds__(256)
__global__ void layer_gather_kernel(const float* __restrict__ y, const float* __restrict__ r,
                                    const float* __restrict__ bias, float* __restrict__ out) {
    const int node = (blockIdx.x * blockDim.x + threadIdx.x) >> 5;
    const int lane = threadIdx.x & 31;
    if (node >= NNODES) return;
    constexpr int C = F / 32;

    float acc[C];
    const float* yi = y + (size_t)node * F + lane;
#pragma unroll
    for (int c = 0; c < C; c++) acc[c] = __ldg(yi + 32 * c);   // self loop

    const int s = g_rowstart[node];
    const int e = g_rowstart[node + 1];
    int p = s;
    for (; p + 4 <= e; p += 4) {
        int i0 = __ldg(&g_csr[p]);
        int i1 = __ldg(&g_csr[p + 1]);
        int i2 = __ldg(&g_csr[p + 2]);
        int i3 = __ldg(&g_csr[p + 3]);
        const float* p0 = y + (size_t)i0 * F + lane;
        const float* p1 = y + (size_t)i1 * F + lane;
        const float* p2 = y + (size_t)i2 * F + lane;
        const float* p3 = y + (size_t)i3 * F + lane;
        float v0[C], v1[C], v2[C], v3[C];
#pragma unroll
        for (int c = 0; c < C; c++) {
            v0[c] = __ldg(p0 + 32 * c);
            v1[c] = __ldg(p1 + 32 * c);
            v2[c] = __ldg(p2 + 32 * c);
            v3[c] = __ldg(p3 + 32 * c);
        }
#pragma unroll
        for (int c = 0; c < C; c++) acc[c] += (v0[c] + v1[c]) + (v2[c] + v3[c]);
    }
    for (; p < e; p++) {
        int j = __ldg(&g_csr[p]);
        const float* pj = y + (size_t)j * F + lane;
#pragma unroll
        for (int c = 0; c < C; c++) acc[c] += __ldg(pj + 32 * c);
    }

    const float di = g_dinv[node];
#pragma unroll
    for (int c = 0; c < C; c++) {
        int f = lane + 32 * c;
        float v = fmaf(di, acc[c], __ldg(r + (size_t)node * F + f) + __ldg(bias + f));
        out[(size_t)node * F + f] = fmaxf(v, 0.f);
    }
}

// Both GCN heads, interleaved [mu|ls] 64-wide buffer (dis[src]-prescaled rows):
// out = dis[i]*(ml[i] + sum_{j->i} ml[j]) + b
__launch_bounds__(256)
__global__ void head_gather2_kernel(const float* __restrict__ ml,
                                    const float* __restrict__ bmu, const float* __restrict__ bls,
                                    float* __restrict__ out) {
    const int node = (blockIdx.x * blockDim.x + threadIdx.x) >> 5;
    const int lane = threadIdx.x & 31;
    if (node >= NNODES) return;

    float a0 = __ldg(ml + (size_t)node * 64 + lane);
    float a1 = __ldg(ml + (size_t)node * 64 + 32 + lane);

    const int s = g_rowstart[node];
    const int e = g_rowstart[node + 1];
    int p = s;
    for (; p + 4 <= e; p += 4) {
        int i0 = __ldg(&g_csr[p]);
        int i1 = __ldg(&g_csr[p + 1]);
        int i2 = __ldg(&g_csr[p + 2]);
        int i3 = __ldg(&g_csr[p + 3]);
        const float* p0 = ml + (size_t)i0 * 64 + lane;
        const float* p1 = ml + (size_t)i1 * 64 + lane;
        const float* p2 = ml + (size_t)i2 * 64 + lane;
        const float* p3 = ml + (size_t)i3 * 64 + lane;
        float m0 = __ldg(p0),      m1 = __ldg(p1),      m2 = __ldg(p2),      m3 = __ldg(p3);
        float l0 = __ldg(p0 + 32), l1 = __ldg(p1 + 32), l2 = __ldg(p2 + 32), l3 = __ldg(p3 + 32);
        a0 += (m0 + m1) + (m2 + m3);
        a1 += (l0 + l1) + (l2 + l3);
    }
    for (; p < e; p++) {
        int j = __ldg(&g_csr[p]);
        a0 += __ldg(ml + (size_t)j * 64 + lane);
        a1 += __ldg(ml + (size_t)j * 64 + 32 + lane);
    }

    const float di = g_dis[node];
    out[(size_t)node * 32 + lane] = fmaf(di, a0, __ldg(bmu + lane));
    out[(size_t)NNODES * 32 + (size_t)node * 32 + lane] = fmaf(di, a1, __ldg(bls + lane));
}

// ---------------- launch ----------------
extern "C" void kernel_launch(void* const* d_in, const int* in_sizes, int n_in,
                              void* d_out, int out_size) {
    (void)in_sizes; (void)n_in; (void)out_size;

    const float* x   = (const float*)d_in[0];
    const int*   ei  = (const int*)d_in[1];
    const float* W1  = (const float*)d_in[2];
    const float* b1  = (const float*)d_in[3];
    const float* Wr1 = (const float*)d_in[4];
    const float* W2  = (const float*)d_in[5];
    const float* b2  = (const float*)d_in[6];
    const float* Wr2 = (const float*)d_in[7];
    const float* Wmu = (const float*)d_in[8];
    const float* bmu = (const float*)d_in[9];
    const float* Wls = (const float*)d_in[10];
    const float* bls = (const float*)d_in[11];
    float* out = (float*)d_out;

    const int* src = ei;
    const int* dst = ei + NEDGES;

    // dynamic smem sizes: (2*128 + 2*NW) * (K+8) * sizeof(bf16)
    constexpr int SM1 = (256 + 2 * 192) * (F_IN + 8) * 2;   // 174080
    constexpr int SM2 = (256 + 2 * 128) * (F_L1 + 8) * 2;   // 106496
    constexpr int SM3 = (256 + 2 * 64)  * (F_L2 + 8) * 2;   //  55296

    static float *p_y = nullptr, *p_r = nullptr, *p_h1 = nullptr, *p_h2 = nullptr,
                 *p_ml = nullptr, *p_dis = nullptr;
    static int *p_degcnt = nullptr;
    if (!p_y) {  // one-time address lookup + smem opt-in (no allocations, no stream ops)
        cudaGetSymbolAddress((void**)&p_y,  g_y);
        cudaGetSymbolAddress((void**)&p_r,  g_r);
        cudaGetSymbolAddress((void**)&p_h1, g_h1);
        cudaGetSymbolAddress((void**)&p_h2, g_h2);
        cudaGetSymbolAddress((void**)&p_ml, g_ml);
        cudaGetSymbolAddress((void**)&p_dis, g_dis);
        cudaGetSymbolAddress((void**)&p_degcnt, g_degcnt);
        cudaFuncSetAttribute(mma_gemm_kernel<F_IN, 192, false>,
                             cudaFuncAttributeMaxDynamicSharedMemorySize, SM1);
        cudaFuncSetAttribute(mma_gemm_kernel<F_L1, 128, false>,
                             cudaFuncAttributeMaxDynamicSharedMemorySize, SM2);
        cudaFuncSetAttribute(mma_gemm_kernel<F_L2, 64, true>,
                             cudaFuncAttributeMaxDynamicSharedMemorySize, SM3);
    }

    constexpr int TB = 256;
    const int gridE  = (NEDGES + TB - 1) / TB;
    const int gridGM = (NNODES + 127) / 128;                 // GEMM row blocks
    const int gridGA = ((size_t)NNODES * 32 + TB - 1) / TB;  // 1 warp / node

    // 1) CSR + normalization factors (parallel 3-stage scan)
    cudaMemsetAsync(p_degcnt, 0, NNODES * sizeof(int));
    count_deg_kernel<<<gridE, TB>>>(dst);
    scan_partial_kernel<<<SCAN_NBLK, SCAN_BLK>>>();
    scan_tops_kernel<<<1, 512>>>();
    scan_final_kernel<<<SCAN_NBLK, SCAN_BLK>>>();
    fill_csr_kernel<<<gridE, TB>>>(src, dst);

    // 2) layer 1: [y|r] = x @ [W1|Wr1], gather+relu
    mma_gemm_kernel<F_IN, 192, false><<<gridGM, TB, SM1>>>(x, W1, Wr1, nullptr, p_y, p_r, 96);
    layer_gather_kernel<F_L1><<<gridGA, TB>>>(p_y, p_r, b1, p_h1);

    // 3) layer 2
    mma_gemm_kernel<F_L1, 128, false><<<gridGM, TB, SM2>>>(p_h1, W2, Wr2, nullptr, p_y, p_r, 64);
    layer_gather_kernel<F_L2><<<gridGA, TB>>>(p_y, p_r, b2, p_h2);

    // 4) GCN heads: one fused GEMM into interleaved [mu|ls] buffer + one fused gather
    mma_gemm_kernel<F_L2, 64, true><<<gridGM, TB, SM3>>>(p_h2, Wmu, Wls, p_dis, p_ml, p_ml + 32, 64);
    head_gather2_kernel<<<gridGA, TB>>>(p_ml, bmu, bls, out);
}